// round 17
// baseline (speedup 1.0000x reference)
#include <cuda_runtime.h>
#include <math.h>

// Problem constants (fixed by reference setup_inputs)
#define BB    512
#define KK    8
#define PP    6
#define DD    1024
#define NIDS  64
#define NGRP  (2 * NIDS)
#define MARGIN 0.2f
#define NPROD (NGRP * PP)         // 768 producer blocks
#define NCONS (BB * PP)           // 3072 consumer blocks
#define GRID  (NPROD + NCONS)

// Scratch (no allocations allowed)
__device__ float g_w[BB];                 // fused per-sample weight
__device__ int   g_goff[NGRP];            // CSR offset per group
__device__ int   g_gcnt[NGRP];            // count per group
__device__ int   g_list[BB];              // CSR sample indices by group
__device__ float g_center[NPROD * DD];    // finished centers [grp][p][D] (3 MB)
__device__ int   g_flag[NPROD];           // center-ready flags (monotone)

// Portable warp-wide float sum (butterfly).
__device__ __forceinline__ float warp_sum(float v) {
#pragma unroll
    for (int s = 16; s; s >>= 1) v += __shfl_xor_sync(0xffffffffu, v, s);
    return v;
}

// ---------------------------------------------------------------------------
// K1: one block, 512 threads. Histogram, validity, id_count, parallel
//     exclusive scan, fused weights, per-group CSR, zero d_out.
// ---------------------------------------------------------------------------
__global__ void k1_setup(const int* __restrict__ pids,
                         const int* __restrict__ camids,
                         float* __restrict__ out) {
    __shared__ int scnt[NGRP];
    __shared__ int scur[NGRP];
    __shared__ int soff[NGRP];
    __shared__ int svalid[NIDS];
    __shared__ int s_idcount;
    __shared__ int warpsum[4];

    int t = threadIdx.x;
    if (t < NGRP) { scnt[t] = 0; scur[t] = 0; }
    if (t == 0) s_idcount = 0;
    __syncthreads();

    int pid = 0, cam = 0, own_grp = 0;
    if (t < BB) {
        pid = pids[t];
        cam = camids[t];
        int mod = (cam == 0) ? 0 : 1;
        own_grp = mod * NIDS + pid;
        atomicAdd(&scnt[own_grp], 1);
    }
    __syncthreads();

    if (t < NIDS) {
        int v = (scnt[t] > 0 && scnt[NIDS + t] > 0) ? 1 : 0;
        svalid[t] = v;
        if (v) atomicAdd(&s_idcount, 1);
    }

    // Parallel exclusive scan of scnt[0..127] using first 4 warps
    int v = 0, inc = 0;
    if (t < NGRP) {
        v = scnt[t];
        inc = v;
        int lane = t & 31;
#pragma unroll
        for (int d = 1; d < 32; d <<= 1) {
            int n = __shfl_up_sync(0xffffffffu, inc, d);
            if (lane >= d) inc += n;
        }
        if (lane == 31) warpsum[t >> 5] = inc;
    }
    __syncthreads();
    if (t == 0) {
        int a = 0;
#pragma unroll
        for (int i = 0; i < 4; ++i) { int x = warpsum[i]; warpsum[i] = a; a += x; }
    }
    __syncthreads();
    if (t < NGRP) {
        int off = inc - v + warpsum[t >> 5];
        soff[t] = off;
        g_goff[t] = off;
        g_gcnt[t] = scnt[t];
    }
    __syncthreads();

    float denom = fmaxf((float)s_idcount, 1.0f);

    if (t < BB) {
        int rgb = (cam == 0);
        float grp_cnt = fmaxf((float)scnt[own_grp], 1.0f);
        float w = svalid[pid] ? (1.0f / (grp_cnt * (float)KK * (float)PP * denom)) : 0.0f;
        g_w[t] = w;
        int pos = atomicAdd(&scur[own_grp], 1);
        g_list[soff[own_grp] + pos] = t;
    }
    if (t == 0) out[0] = 0.0f;
}

// ---------------------------------------------------------------------------
// K4: producers (bid < NPROD) build one center row each and publish it;
//     consumers (bid >= NPROD) stage own row, spin-load the finished center,
//     then stream their 8 k-rows of f_gen (evict-first batched loads).
// ---------------------------------------------------------------------------
__global__ void __launch_bounds__(256) k4_main(const float* __restrict__ f_orig,
                                               const float* __restrict__ f_gen,
                                               const int*   __restrict__ pids,
                                               const int*   __restrict__ camids,
                                               float*       __restrict__ out) {
    __shared__ float so[DD];
    __shared__ float sc[DD];
    __shared__ float spart[8];

    int bid = blockIdx.x;
    int t = threadIdx.x;
    int w = t >> 5;
    int lane = t & 31;
    const float4* fo4 = reinterpret_cast<const float4*>(f_orig);

    if (bid < NPROD) {
        // ---------------- Producer: center for (grp, p) ----------------
        int grp = bid / PP;
        int p = bid - grp * PP;

        asm volatile("griddepcontrol.wait;" ::: "memory");

        int off = g_goff[grp];
        int cnt = g_gcnt[grp];
        float cinv = 1.0f / fmaxf((float)cnt, 1.0f);
        float4 acc = make_float4(0.f, 0.f, 0.f, 0.f);
        int j = 0;
        for (; j + 4 <= cnt; j += 4) {
            int b0 = g_list[off + j + 0], b1 = g_list[off + j + 1];
            int b2 = g_list[off + j + 2], b3 = g_list[off + j + 3];
            float4 v0 = fo4[(((size_t)(b0 * PP + p) * DD) >> 2) + t];
            float4 v1 = fo4[(((size_t)(b1 * PP + p) * DD) >> 2) + t];
            float4 v2 = fo4[(((size_t)(b2 * PP + p) * DD) >> 2) + t];
            float4 v3 = fo4[(((size_t)(b3 * PP + p) * DD) >> 2) + t];
            acc.x += (v0.x + v1.x) + (v2.x + v3.x);
            acc.y += (v0.y + v1.y) + (v2.y + v3.y);
            acc.z += (v0.z + v1.z) + (v2.z + v3.z);
            acc.w += (v0.w + v1.w) + (v2.w + v3.w);
        }
        for (; j < cnt; ++j) {
            int bs = g_list[off + j];
            float4 vv = fo4[(((size_t)(bs * PP + p) * DD) >> 2) + t];
            acc.x += vv.x; acc.y += vv.y; acc.z += vv.z; acc.w += vv.w;
        }
        acc.x *= cinv; acc.y *= cinv; acc.z *= cinv; acc.w *= cinv;
        reinterpret_cast<float4*>(g_center)[(size_t)bid * (DD / 4) + t] = acc;
        __syncthreads();
        if (t == 0) {
            __threadfence();
            atomicExch(&g_flag[bid], 1);
        }
        return;
    }

    // ------------------- Consumer: tile (b, p) ---------------------------
    int bp = bid - NPROD;
    int b = bp / PP;
    int p = bp - b * PP;

    float4* so4 = reinterpret_cast<float4*>(so);
    float4* sc4 = reinterpret_cast<float4*>(sc);

    // Pre-wait: stage own row + compute flag index from raw inputs
    so4[t] = fo4[(((size_t)(b * PP + p) * DD) >> 2) + t];
    int pid_b = pids[b];
    int cross_mod = (camids[b] == 0) ? 1 : 0;
    int fid = (cross_mod * NIDS + pid_b) * PP + p;

    asm volatile("griddepcontrol.wait;" ::: "memory");

    // Spin until center published (t0 polls; usually already set)
    if (t == 0) {
        while (atomicAdd(&g_flag[fid], 0) == 0) { }
        __threadfence();
    }
    __syncthreads();

    // Single coalesced center-row load (L2-resident, just written)
    sc4[t] = reinterpret_cast<const float4*>(g_center)[(size_t)fid * (DD / 4) + t];
    __syncthreads();

    // Main stream: warp w handles f_generated[b, w, p, :] (evict-first)
    const float4* gp = reinterpret_cast<const float4*>(
        f_gen + ((size_t)((b * KK + w) * PP + p)) * DD);

    float4 g[8];
#pragma unroll
    for (int it = 0; it < 8; ++it) g[it] = __ldcs(&gp[it * 32 + lane]);

    float s_pull = 0.0f, s_push = 0.0f;
#pragma unroll
    for (int it = 0; it < 8; ++it) {
        float4 o = so4[it * 32 + lane];
        float4 c = sc4[it * 32 + lane];
        float dx, dy, dz, dw;
        dx = g[it].x - c.x; dy = g[it].y - c.y;
        dz = g[it].z - c.z; dw = g[it].w - c.w;
        s_pull += dx * dx + dy * dy + dz * dz + dw * dw;
        dx = g[it].x - o.x; dy = g[it].y - o.y;
        dz = g[it].z - o.z; dw = g[it].w - o.w;
        s_push += dx * dx + dy * dy + dz * dz + dw * dw;
    }

    s_pull = warp_sum(s_pull);
    s_push = warp_sum(s_push);

    if (lane == 0) {
        float h = sqrtf(s_pull) - sqrtf(s_push) + MARGIN;
        spart[w] = fmaxf(h, 0.0f);
    }
    __syncthreads();
    if (t == 0) {
        float s = 0.0f;
#pragma unroll
        for (int i = 0; i < 8; ++i) s += spart[i];
        atomicAdd(out, s * g_w[b]);
    }
}

// ---------------------------------------------------------------------------
extern "C" void kernel_launch(void* const* d_in, const int* in_sizes, int n_in,
                              void* d_out, int out_size) {
    const float* f_orig = (const float*)d_in[0];
    const float* f_gen  = (const float*)d_in[1];
    const int*   pids   = (const int*)d_in[2];
    const int*   camids = (const int*)d_in[3];
    float*       out    = (float*)d_out;

    k1_setup<<<1, 512>>>(pids, camids, out);

    // PDL: k4 launches while k1 drains; k4 syncs via griddepcontrol.wait
    cudaLaunchConfig_t cfg = {};
    cfg.gridDim  = dim3(GRID);
    cfg.blockDim = dim3(256);
    cfg.dynamicSmemBytes = 0;
    cfg.stream = 0;
    cudaLaunchAttribute attrs[1];
    attrs[0].id = cudaLaunchAttributeProgrammaticStreamSerialization;
    attrs[0].val.programmaticStreamSerializationAllowed = 1;
    cfg.attrs = attrs;
    cfg.numAttrs = 1;
    cudaLaunchKernelEx(&cfg, k4_main, f_orig, f_gen, pids, camids, out);
}